// round 6
// baseline (speedup 1.0000x reference)
#include <cuda_runtime.h>
#include <cuda_fp16.h>
#include <cstddef>
#include <cstdint>

#define BB 64
#define NN 2048
#define II 16
#define JJ 32
#define OO 32
#define JO 1024      // J*O
#define NCHUNK 16
#define CHUNK 128    // NN / NCHUNK

// Scratch (allocation-free rule: __device__ globals).
__device__ __half g_predh[(size_t)BB * NN * JO];               // 256 MB fp16 predictions
__device__ float g_partial[(size_t)NCHUNK * BB * JO];          // per-chunk partial s sums
__device__ float g_blog[(size_t)BB * NN * JJ];                 // routing logits (pass1 -> pass2)

// ---- packed fp32x2 helpers (sm_103a) --------------------------------------
__device__ __forceinline__ unsigned long long pk2(float a, float b) {
    unsigned long long r;
    asm("mov.b64 %0, {%1, %2};" : "=l"(r) : "f"(a), "f"(b));
    return r;
}
__device__ __forceinline__ void ffma2(unsigned long long& d,
                                      unsigned long long a,
                                      unsigned long long b) {
    asm("fma.rn.f32x2 %0, %1, %2, %0;" : "+l"(d) : "l"(a), "l"(b));
}
__device__ __forceinline__ float2 up2(unsigned long long v) {
    float2 f;
    asm("mov.b64 {%0, %1}, %2;" : "=f"(f.x), "=f"(f.y) : "l"(v));
    return f;
}
__device__ __forceinline__ float4 h4_to_f4(uint2 u) {
    __half2 h0 = *reinterpret_cast<__half2*>(&u.x);
    __half2 h1 = *reinterpret_cast<__half2*>(&u.y);
    float2 a = __half22float2(h0);
    float2 c = __half22float2(h1);
    return make_float4(a.x, a.y, c.x, c.y);
}

// ---------------------------------------------------------------------------
// K1: predictions via packed f32x2 FFMA. One CTA per n, 256 threads; thread t
// owns jo in [4t,4t+4). Weight pairs packed once into 64-bit regs; x stored
// duplicated (x,x) in smem and loaded as 64-bit pairs (broadcast LDS.128).
// Output fp16.
// ---------------------------------------------------------------------------
__global__ __launch_bounds__(256, 2)
void pred_kernel(const float* __restrict__ x, const float* __restrict__ w) {
    const int n = blockIdx.x;
    const int t = threadIdx.x;

    __shared__ float2 xs2[BB][II];   // (x,x) duplicated pairs, 8 KB
    {
        int b = t >> 2, q = t & 3;
        float4 f = reinterpret_cast<const float4*>(x + ((size_t)b * NN + n) * II)[q];
        xs2[b][4 * q + 0] = make_float2(f.x, f.x);
        xs2[b][4 * q + 1] = make_float2(f.y, f.y);
        xs2[b][4 * q + 2] = make_float2(f.z, f.z);
        xs2[b][4 * q + 3] = make_float2(f.w, f.w);
    }

    float wr[4][16];
    const float4* wp = reinterpret_cast<const float4*>(w + ((size_t)n * JO + 4 * t) * II);
#pragma unroll
    for (int q = 0; q < 4; ++q) {
#pragma unroll
        for (int c = 0; c < 4; ++c) {
            float4 f = wp[q * 4 + c];
            wr[q][4 * c + 0] = f.x; wr[q][4 * c + 1] = f.y;
            wr[q][4 * c + 2] = f.z; wr[q][4 * c + 3] = f.w;
        }
    }
    unsigned long long wp01[16], wp23[16];
#pragma unroll
    for (int i = 0; i < 16; ++i) {
        wp01[i] = pk2(wr[0][i], wr[1][i]);
        wp23[i] = pk2(wr[2][i], wr[3][i]);
    }
    __syncthreads();

    __half* outp = g_predh + (size_t)n * JO + 4 * t;
    uint32_t xbase = (uint32_t)__cvta_generic_to_shared(&xs2[0][0]);

#pragma unroll 4
    for (int b = 0; b < BB; ++b) {
        uint32_t xa = xbase + b * (II * 8);
        unsigned long long acc01 = 0ull, acc23 = 0ull;
#pragma unroll
        for (int k = 0; k < 8; ++k) {
            unsigned long long xx0, xx1;
            asm("ld.shared.v2.u64 {%0, %1}, [%2];"
                : "=l"(xx0), "=l"(xx1) : "r"(xa + k * 16));
            ffma2(acc01, xx0, wp01[2 * k]);
            ffma2(acc23, xx0, wp23[2 * k]);
            ffma2(acc01, xx1, wp01[2 * k + 1]);
            ffma2(acc23, xx1, wp23[2 * k + 1]);
        }
        float2 a01 = up2(acc01);
        float2 a23 = up2(acc23);
        __half2 b01 = __float22half2_rn(a01);
        __half2 b23 = __float22half2_rn(a23);
        uint2 st;
        st.x = *reinterpret_cast<unsigned int*>(&b01);
        st.y = *reinterpret_cast<unsigned int*>(&b23);
        *reinterpret_cast<uint2*>(outp + (size_t)b * NN * JO) = st;
    }
}

// ---------------------------------------------------------------------------
// K2: iter-0 s (uniform coupling). Pure streaming sum; deep unroll for MLP.
// ---------------------------------------------------------------------------
__global__ __launch_bounds__(256)
void sum0_kernel() {
    const int chunk = blockIdx.x;
    const int b = blockIdx.y;
    const int t = threadIdx.x;
    const uint2* predp = reinterpret_cast<const uint2*>(
        g_predh + ((size_t)b * NN + (size_t)chunk * CHUNK) * JO);

    float4 sacc = make_float4(0.f, 0.f, 0.f, 0.f);
#pragma unroll 16
    for (int n = 0; n < CHUNK; ++n) {
        float4 p = h4_to_f4(predp[(size_t)n * (JO / 4) + t]);
        sacc.x += p.x; sacc.y += p.y; sacc.z += p.z; sacc.w += p.w;
    }
    const float inv = 1.0f / 32.0f;
    sacc.x *= inv; sacc.y *= inv; sacc.z *= inv; sacc.w *= inv;
    reinterpret_cast<float4*>(g_partial + ((size_t)chunk * BB + b) * JO)[t] = sacc;
}

// ---------------------------------------------------------------------------
// K3: routing pass (iters 1,2), barrier-free warp-per-n mainloop.
// Grid (NCHUNK, BB), 256 threads = 8 warps; warp w owns n = chunk*128+w*16+i.
// Prologue (cooperative): s from g_partial, squash -> v into smem, 1 barrier.
// Mainloop per n (per warp, no barriers):
//   4 coalesced LDG.128 -> lane l holds 8-elem slices of j = q*8+(l>>2)
//   dot partials, 2 shuffles per q -> full dots; lane owns j=(l&3)*8+(l>>2)
//   blog (MODE1 store / MODE2 add), 32-lane shuffle softmax, 1 exp/lane
//   c broadcast (4 shuffles), fp32 sacc accumulate in regs.
// Epilogue: 8-warp sacc reduction through smem, 1 barrier, write partials.
// ---------------------------------------------------------------------------
template <int MODE>
__global__ __launch_bounds__(256, 2)
void pass_kernel() {
    const int chunk = blockIdx.x;
    const int b = blockIdx.y;
    const int t = threadIdx.x;
    const int warp = t >> 5;
    const int lane = t & 31;

    __shared__ float v_sm[JO];          // 4 KB
    __shared__ float s_red[8][JO];      // 32 KB

    // ---- prologue: s = sum of partials; v = squash(s) -> v_sm ----
    {
        float4 sv = make_float4(0.f, 0.f, 0.f, 0.f);
#pragma unroll
        for (int k = 0; k < NCHUNK; ++k) {
            float4 p = reinterpret_cast<const float4*>(
                g_partial + ((size_t)k * BB + b) * JO)[t];
            sv.x += p.x; sv.y += p.y; sv.z += p.z; sv.w += p.w;
        }
        float sq = sv.x * sv.x + sv.y * sv.y + sv.z * sv.z + sv.w * sv.w;
        sq += __shfl_xor_sync(0xffffffffu, sq, 1);
        sq += __shfl_xor_sync(0xffffffffu, sq, 2);
        sq += __shfl_xor_sync(0xffffffffu, sq, 4);
        float scale = (sq / (1.0f + sq)) * rsqrtf(sq + 1e-8f);
        reinterpret_cast<float4*>(v_sm)[t] =
            make_float4(sv.x * scale, sv.y * scale, sv.z * scale, sv.w * scale);
    }
    __syncthreads();

    // lane's v slices: v[q][e] = v[(q*8+(lane>>2))*32 + (lane&3)*8 + e]
    float v[4][8];
#pragma unroll
    for (int q = 0; q < 4; ++q) {
        const float4* vp = reinterpret_cast<const float4*>(
            v_sm + (q * 8 + (lane >> 2)) * 32 + (lane & 3) * 8);
        float4 a0 = vp[0], a1 = vp[1];
        v[q][0] = a0.x; v[q][1] = a0.y; v[q][2] = a0.z; v[q][3] = a0.w;
        v[q][4] = a1.x; v[q][5] = a1.y; v[q][6] = a1.z; v[q][7] = a1.w;
    }

    const int jown = (lane & 3) * 8 + (lane >> 2);
    float sacc[4][8];
#pragma unroll
    for (int q = 0; q < 4; ++q)
#pragma unroll
        for (int e = 0; e < 8; ++e) sacc[q][e] = 0.f;

    const uint4* pbase = reinterpret_cast<const uint4*>(
        g_predh + ((size_t)b * NN + (size_t)chunk * CHUNK + warp * 16) * JO);
    const size_t blogbase =
        ((size_t)b * NN + (size_t)chunk * CHUNK + warp * 16) * JJ + jown;

    for (int i = 0; i < 16; ++i) {
        uint4 cur[4];
#pragma unroll
        for (int q = 0; q < 4; ++q)
            cur[q] = pbase[(size_t)i * 128 + q * 32 + lane];

        // partial dots (fp32)
        float d[4];
#pragma unroll
        for (int q = 0; q < 4; ++q) {
            float2 f0 = __half22float2(*reinterpret_cast<__half2*>(&cur[q].x));
            float2 f1 = __half22float2(*reinterpret_cast<__half2*>(&cur[q].y));
            float2 f2 = __half22float2(*reinterpret_cast<__half2*>(&cur[q].z));
            float2 f3 = __half22float2(*reinterpret_cast<__half2*>(&cur[q].w));
            float dd = f0.x * v[q][0];
            dd = fmaf(f0.y, v[q][1], dd);
            dd = fmaf(f1.x, v[q][2], dd);
            dd = fmaf(f1.y, v[q][3], dd);
            dd = fmaf(f2.x, v[q][4], dd);
            dd = fmaf(f2.y, v[q][5], dd);
            dd = fmaf(f3.x, v[q][6], dd);
            dd = fmaf(f3.y, v[q][7], dd);
            d[q] = dd;
        }
        // finish dots within 4-lane o-groups
#pragma unroll
        for (int q = 0; q < 4; ++q) {
            d[q] += __shfl_xor_sync(0xffffffffu, d[q], 1);
            d[q] += __shfl_xor_sync(0xffffffffu, d[q], 2);
        }
        // lane takes the dot of its owned capsule jown (q = lane&3)
        float a = (lane & 1) ? ((lane & 2) ? d[3] : d[1])
                             : ((lane & 2) ? d[2] : d[0]);

        const size_t bidx = blogbase + (size_t)i * JJ;
        if (MODE == 2) a += g_blog[bidx];
        else           g_blog[bidx] = a;      // b1 = agreement (b0 = 0)

        // softmax over the 32 capsules (one value per lane)
        float m = a;
#pragma unroll
        for (int s = 16; s > 0; s >>= 1)
            m = fmaxf(m, __shfl_xor_sync(0xffffffffu, m, s));
        float e = __expf(a - m);
        float ssum = e;
#pragma unroll
        for (int s = 16; s > 0; s >>= 1)
            ssum += __shfl_xor_sync(0xffffffffu, ssum, s);
        float c = e / ssum;                   // coupling for capsule jown

        // accumulate: lane needs c of j = q*8+(lane>>2), owned by (lane&~3)+q
#pragma unroll
        for (int q = 0; q < 4; ++q) {
            float cq = __shfl_sync(0xffffffffu, c, (lane & ~3) + q);
            float2 f0 = __half22float2(*reinterpret_cast<__half2*>(&cur[q].x));
            float2 f1 = __half22float2(*reinterpret_cast<__half2*>(&cur[q].y));
            float2 f2 = __half22float2(*reinterpret_cast<__half2*>(&cur[q].z));
            float2 f3 = __half22float2(*reinterpret_cast<__half2*>(&cur[q].w));
            sacc[q][0] = fmaf(cq, f0.x, sacc[q][0]);
            sacc[q][1] = fmaf(cq, f0.y, sacc[q][1]);
            sacc[q][2] = fmaf(cq, f1.x, sacc[q][2]);
            sacc[q][3] = fmaf(cq, f1.y, sacc[q][3]);
            sacc[q][4] = fmaf(cq, f2.x, sacc[q][4]);
            sacc[q][5] = fmaf(cq, f2.y, sacc[q][5]);
            sacc[q][6] = fmaf(cq, f3.x, sacc[q][6]);
            sacc[q][7] = fmaf(cq, f3.y, sacc[q][7]);
        }
    }

    // epilogue: combine the 8 warps' sacc
#pragma unroll
    for (int q = 0; q < 4; ++q) {
        float* dst = &s_red[warp][q * 256 + lane * 8];
        reinterpret_cast<float4*>(dst)[0] =
            make_float4(sacc[q][0], sacc[q][1], sacc[q][2], sacc[q][3]);
        reinterpret_cast<float4*>(dst)[1] =
            make_float4(sacc[q][4], sacc[q][5], sacc[q][6], sacc[q][7]);
    }
    __syncthreads();
    float4 o = make_float4(0.f, 0.f, 0.f, 0.f);
#pragma unroll
    for (int w = 0; w < 8; ++w) {
        float4 p = reinterpret_cast<const float4*>(s_red[w])[t];
        o.x += p.x; o.y += p.y; o.z += p.z; o.w += p.w;
    }
    reinterpret_cast<float4*>(g_partial + ((size_t)chunk * BB + b) * JO)[t] = o;
}

// ---------------------------------------------------------------------------
// K4: final reduce + squash -> d_out. One block per b, thread t = jo.
// ---------------------------------------------------------------------------
__global__ __launch_bounds__(1024)
void squash_kernel(float* __restrict__ out) {
    const int b = blockIdx.x;
    const int t = threadIdx.x;
    float s = 0.f;
#pragma unroll
    for (int k = 0; k < NCHUNK; ++k)
        s += g_partial[((size_t)k * BB + b) * JO + t];
    float sq = s * s;
#pragma unroll
    for (int m = 16; m > 0; m >>= 1)
        sq += __shfl_xor_sync(0xffffffffu, sq, m);
    float scale = (sq / (1.0f + sq)) * rsqrtf(sq + 1e-8f);
    out[b * JO + t] = s * scale;
}

// ---------------------------------------------------------------------------
extern "C" void kernel_launch(void* const* d_in, const int* in_sizes, int n_in,
                              void* d_out, int out_size) {
    const float* x = (const float*)d_in[0];   // [64, 2048, 16] f32
    const float* w = (const float*)d_in[1];   // [2048, 32, 32, 16] f32
    float* out = (float*)d_out;               // [64, 32, 32] f32

    dim3 pg(NCHUNK, BB);
    pred_kernel<<<NN, 256>>>(x, w);
    sum0_kernel<<<pg, 256>>>();               // iter 0: uniform c -> s0 partials
    pass_kernel<1><<<pg, 256>>>();            // v0 (prologue) -> b1 -> c1 -> s1
    pass_kernel<2><<<pg, 256>>>();            // v1 (prologue) -> b2 -> c2 -> s2
    squash_kernel<<<BB, 1024>>>(out);         // v2 -> output
}

// round 7
// speedup vs baseline: 1.0341x; 1.0341x over previous
#include <cuda_runtime.h>
#include <cuda_fp16.h>
#include <cstddef>
#include <cstdint>

#define BB 64
#define NN 2048
#define II 16
#define JJ 32
#define OO 32
#define JO 1024      // J*O
#define NB 8         // n's per barrier round in pass_kernel (== #warps)
#define CHUNK 128    // n's per pass CTA (16 chunks)
#define NCH0 32      // sum0 chunks
#define CH0 64       // n's per sum0 CTA

// Scratch (allocation-free rule: __device__ globals).
__device__ __half g_predh[(size_t)BB * NN * JO];        // 256 MB fp16 predictions
__device__ float g_pA[(size_t)NCH0 * BB * JO];          // partial buffer A (8 MB)
__device__ float g_pB[(size_t)16 * BB * JO];            // partial buffer B (4 MB)
__device__ float g_v[BB * JO];                          // squashed v
__device__ float g_blog[(size_t)BB * NN * JJ];          // routing logits (pass1 -> pass2)

// ---- packed fp32x2 helpers (sm_103a) --------------------------------------
__device__ __forceinline__ unsigned long long pk2(float a, float b) {
    unsigned long long r;
    asm("mov.b64 %0, {%1, %2};" : "=l"(r) : "f"(a), "f"(b));
    return r;
}
__device__ __forceinline__ void ffma2(unsigned long long& d,
                                      unsigned long long a,
                                      unsigned long long b) {
    asm("fma.rn.f32x2 %0, %1, %2, %0;" : "+l"(d) : "l"(a), "l"(b));
}
__device__ __forceinline__ float2 up2(unsigned long long v) {
    float2 f;
    asm("mov.b64 {%0, %1}, %2;" : "=f"(f.x), "=f"(f.y) : "l"(v));
    return f;
}
__device__ __forceinline__ float4 h4_to_f4(uint2 u) {
    __half2 h0 = *reinterpret_cast<__half2*>(&u.x);
    __half2 h1 = *reinterpret_cast<__half2*>(&u.y);
    float2 a = __half22float2(h0);
    float2 c = __half22float2(h1);
    return make_float4(a.x, a.y, c.x, c.y);
}

// ---------------------------------------------------------------------------
// K1: predictions via packed f32x2 FFMA. One CTA per n, 256 threads; thread t
// owns jo in [4t,4t+4). Weight pairs packed once into 64-bit regs; x stored
// duplicated (x,x) in smem, loaded as 64-bit pairs (broadcast LDS.128).
// ---------------------------------------------------------------------------
__global__ __launch_bounds__(256, 2)
void pred_kernel(const float* __restrict__ x, const float* __restrict__ w) {
    const int n = blockIdx.x;
    const int t = threadIdx.x;

    __shared__ float2 xs2[BB][II];   // (x,x) duplicated pairs, 8 KB
    {
        int b = t >> 2, q = t & 3;
        float4 f = reinterpret_cast<const float4*>(x + ((size_t)b * NN + n) * II)[q];
        xs2[b][4 * q + 0] = make_float2(f.x, f.x);
        xs2[b][4 * q + 1] = make_float2(f.y, f.y);
        xs2[b][4 * q + 2] = make_float2(f.z, f.z);
        xs2[b][4 * q + 3] = make_float2(f.w, f.w);
    }

    float wr[4][16];
    const float4* wp = reinterpret_cast<const float4*>(w + ((size_t)n * JO + 4 * t) * II);
#pragma unroll
    for (int q = 0; q < 4; ++q) {
#pragma unroll
        for (int c = 0; c < 4; ++c) {
            float4 f = wp[q * 4 + c];
            wr[q][4 * c + 0] = f.x; wr[q][4 * c + 1] = f.y;
            wr[q][4 * c + 2] = f.z; wr[q][4 * c + 3] = f.w;
        }
    }
    unsigned long long wp01[16], wp23[16];
#pragma unroll
    for (int i = 0; i < 16; ++i) {
        wp01[i] = pk2(wr[0][i], wr[1][i]);
        wp23[i] = pk2(wr[2][i], wr[3][i]);
    }
    __syncthreads();

    __half* outp = g_predh + (size_t)n * JO + 4 * t;
    uint32_t xbase = (uint32_t)__cvta_generic_to_shared(&xs2[0][0]);

#pragma unroll 4
    for (int b = 0; b < BB; ++b) {
        uint32_t xa = xbase + b * (II * 8);
        unsigned long long acc01 = 0ull, acc23 = 0ull;
#pragma unroll
        for (int k = 0; k < 8; ++k) {
            unsigned long long xx0, xx1;
            asm("ld.shared.v2.u64 {%0, %1}, [%2];"
                : "=l"(xx0), "=l"(xx1) : "r"(xa + k * 16));
            ffma2(acc01, xx0, wp01[2 * k]);
            ffma2(acc23, xx0, wp23[2 * k]);
            ffma2(acc01, xx1, wp01[2 * k + 1]);
            ffma2(acc23, xx1, wp23[2 * k + 1]);
        }
        float2 a01 = up2(acc01);
        float2 a23 = up2(acc23);
        __half2 b01 = __float22half2_rn(a01);
        __half2 b23 = __float22half2_rn(a23);
        uint2 st;
        st.x = *reinterpret_cast<unsigned int*>(&b01);
        st.y = *reinterpret_cast<unsigned int*>(&b23);
        *reinterpret_cast<uint2*>(outp + (size_t)b * NN * JO) = st;
    }
}

// ---------------------------------------------------------------------------
// K2: iter-0 s partials (uniform coupling). Pure streaming; 128 threads, one
// uint4 (8 jo) per thread per n, unroll-8 for MLP. Writes g_pA (32 chunks).
// ---------------------------------------------------------------------------
__global__ __launch_bounds__(128)
void sum0_kernel() {
    const int chunk = blockIdx.x;   // 0..31
    const int b = blockIdx.y;
    const int t = threadIdx.x;      // octet index 0..127
    const uint4* predp = reinterpret_cast<const uint4*>(
        g_predh + ((size_t)b * NN + (size_t)chunk * CH0) * JO);

    float sacc[8];
#pragma unroll
    for (int e = 0; e < 8; ++e) sacc[e] = 0.f;

#pragma unroll 8
    for (int n = 0; n < CH0; ++n) {
        uint4 r = predp[(size_t)n * 128 + t];
        float2 f0 = __half22float2(*reinterpret_cast<__half2*>(&r.x));
        float2 f1 = __half22float2(*reinterpret_cast<__half2*>(&r.y));
        float2 f2 = __half22float2(*reinterpret_cast<__half2*>(&r.z));
        float2 f3 = __half22float2(*reinterpret_cast<__half2*>(&r.w));
        sacc[0] += f0.x; sacc[1] += f0.y; sacc[2] += f1.x; sacc[3] += f1.y;
        sacc[4] += f2.x; sacc[5] += f2.y; sacc[6] += f3.x; sacc[7] += f3.y;
    }
    const float inv = 1.0f / 32.0f;
    float* dst = g_pA + ((size_t)chunk * BB + b) * JO + t * 8;
    reinterpret_cast<float4*>(dst)[0] =
        make_float4(sacc[0] * inv, sacc[1] * inv, sacc[2] * inv, sacc[3] * inv);
    reinterpret_cast<float4*>(dst)[1] =
        make_float4(sacc[4] * inv, sacc[5] * inv, sacc[6] * inv, sacc[7] * inv);
}

// ---------------------------------------------------------------------------
// K3: reduce partials + squash -> g_v (and optionally d_out). One block per b,
// thread t = jo, warp = capsule j (t consecutive => warp-aligned capsules).
// ---------------------------------------------------------------------------
template <int NCHIN, bool INA>
__global__ __launch_bounds__(1024)
void v_kernel(float* __restrict__ out) {
    const float* pin = INA ? g_pA : g_pB;
    const int b = blockIdx.x;
    const int t = threadIdx.x;
    float s = 0.f;
#pragma unroll
    for (int k = 0; k < NCHIN; ++k)
        s += pin[((size_t)k * BB + b) * JO + t];
    float sq = s * s;
#pragma unroll
    for (int m = 16; m > 0; m >>= 1)
        sq += __shfl_xor_sync(0xffffffffu, sq, m);
    float scale = (sq / (1.0f + sq)) * rsqrtf(sq + 1e-8f);
    float v = s * scale;
    g_v[b * JO + t] = v;
    if (out) out[b * JO + t] = v;
}

// ---------------------------------------------------------------------------
// K4: routing pass (iters 1,2). R5 structure + double-buffered prefetch:
// next round's 8 pred loads are issued BEFORE the two barriers so DRAM stays
// busy during the softmax phase. Reads v from g_v; writes 16-chunk partials
// to the opposite buffer (no cross-CTA read/write races).
//   MODE 1: a = pred.v,  blog = a, softmax(a)
//   MODE 2: a = blog + pred.v,    softmax(a)
// ---------------------------------------------------------------------------
template <int MODE, bool OUTA>
__global__ __launch_bounds__(256, 3)
void pass_kernel() {
    const int chunk = blockIdx.x;
    const int b = blockIdx.y;
    const int t = threadIdx.x;
    const int warp = t >> 5;
    const int lane = t & 31;
    const int j = t >> 3;         // capsule of this thread's quad
    const int sub = t & 7;        // which eighth of capsule j

    __shared__ float a_part[NB][JJ][8];   // 8 KB partial dots
    __shared__ float c_buf[NB][JJ];       // 1 KB couplings

    const float4 vv = reinterpret_cast<const float4*>(g_v + b * JO)[t];

    float4 sacc = make_float4(0.f, 0.f, 0.f, 0.f);
    const uint2* predp = reinterpret_cast<const uint2*>(
        g_predh + ((size_t)b * NN + (size_t)chunk * CHUNK) * JO);

    uint2 raw[NB], rawn[NB];
#pragma unroll
    for (int k = 0; k < NB; ++k)
        raw[k] = predp[(size_t)k * (JO / 4) + t];

#pragma unroll 2
    for (int n0 = 0; n0 < CHUNK; n0 += NB) {
        // prefetch next round (completes during the softmax phase)
        if (n0 + NB < CHUNK) {
#pragma unroll
            for (int k = 0; k < NB; ++k)
                rawn[k] = predp[(size_t)(n0 + NB + k) * (JO / 4) + t];
        }

        // dot partials -> smem (contiguous per warp: conflict-free)
#pragma unroll
        for (int k = 0; k < NB; ++k) {
            float4 p = h4_to_f4(raw[k]);
            a_part[k][j][sub] =
                p.x * vv.x + p.y * vv.y + p.z * vv.z + p.w * vv.w;
        }
        __syncthreads();

        {   // warp k handles n0+k: finish dot, blog, softmax over 32 capsules
            const int k = warp;
            const int n = chunk * CHUNK + n0 + k;
            float4 q0 = *reinterpret_cast<const float4*>(&a_part[k][lane][0]);
            float4 q1 = *reinterpret_cast<const float4*>(&a_part[k][lane][4]);
            float a = ((q0.x + q0.y) + (q0.z + q0.w)) +
                      ((q1.x + q1.y) + (q1.z + q1.w));
            size_t bidx = ((size_t)b * NN + n) * JJ + lane;
            if (MODE == 2) a += g_blog[bidx];
            else           g_blog[bidx] = a;     // b1 = agreement (b0 = 0)
            float m = a;
#pragma unroll
            for (int s = 16; s > 0; s >>= 1)
                m = fmaxf(m, __shfl_xor_sync(0xffffffffu, m, s));
            float e = __expf(a - m);
            float ssum = e;
#pragma unroll
            for (int s = 16; s > 0; s >>= 1)
                ssum += __shfl_xor_sync(0xffffffffu, ssum, s);
            c_buf[k][lane] = e / ssum;
        }
        __syncthreads();

#pragma unroll
        for (int k = 0; k < NB; ++k) {
            float c = c_buf[k][j];
            float4 p = h4_to_f4(raw[k]);
            sacc.x = fmaf(c, p.x, sacc.x);
            sacc.y = fmaf(c, p.y, sacc.y);
            sacc.z = fmaf(c, p.z, sacc.z);
            sacc.w = fmaf(c, p.w, sacc.w);
        }
        if (n0 + NB < CHUNK) {
#pragma unroll
            for (int k = 0; k < NB; ++k) raw[k] = rawn[k];
        }
    }
    float* pout = OUTA ? g_pA : g_pB;
    reinterpret_cast<float4*>(pout + ((size_t)chunk * BB + b) * JO)[t] = sacc;
}

// ---------------------------------------------------------------------------
extern "C" void kernel_launch(void* const* d_in, const int* in_sizes, int n_in,
                              void* d_out, int out_size) {
    const float* x = (const float*)d_in[0];   // [64, 2048, 16] f32
    const float* w = (const float*)d_in[1];   // [2048, 32, 32, 16] f32
    float* out = (float*)d_out;               // [64, 32, 32] f32

    pred_kernel<<<NN, 256>>>(x, w);
    sum0_kernel<<<dim3(NCH0, BB), 128>>>();            // s0 partials -> A (32)
    v_kernel<NCH0, true><<<BB, 1024>>>(nullptr);       // v0
    pass_kernel<1, false><<<dim3(16, BB), 256>>>();    // b1, c1, s1 -> B (16)
    v_kernel<16, false><<<BB, 1024>>>(nullptr);        // v1
    pass_kernel<2, true><<<dim3(16, BB), 256>>>();     // b2, c2, s2 -> A (16)
    v_kernel<16, true><<<BB, 1024>>>(out);             // v2 -> output
}

// round 9
// speedup vs baseline: 1.0410x; 1.0067x over previous
#include <cuda_runtime.h>
#include <cuda_fp16.h>
#include <cstddef>
#include <cstdint>

#define BB 64
#define NN 2048
#define II 16
#define JJ 32
#define OO 32
#define JO 1024      // J*O
#define NB 8         // n's per stage/round in pass_kernel (== #warps)
#define CHUNK 128    // n's per pass CTA (16 chunks)
#define NROUND 16    // CHUNK / NB
#define STAGE_BYTES (NB * JO * 2)   // 16 KB
#define NCH0 32      // sum0 chunks
#define CH0 64       // n's per sum0 CTA

// Scratch (allocation-free rule: __device__ globals).
__device__ __half g_predh[(size_t)BB * NN * JO];        // 256 MB fp16 predictions
__device__ float g_pA[(size_t)NCH0 * BB * JO];          // partial buffer A (8 MB)
__device__ float g_pB[(size_t)16 * BB * JO];            // partial buffer B (4 MB)
__device__ float g_v[BB * JO];                          // squashed v
__device__ float g_blog[(size_t)BB * NN * JJ];          // routing logits (pass1 -> pass2)

// ---- packed fp32x2 helpers (sm_103a) --------------------------------------
__device__ __forceinline__ unsigned long long pk2(float a, float b) {
    unsigned long long r;
    asm("mov.b64 %0, {%1, %2};" : "=l"(r) : "f"(a), "f"(b));
    return r;
}
__device__ __forceinline__ void ffma2(unsigned long long& d,
                                      unsigned long long a,
                                      unsigned long long b) {
    asm("fma.rn.f32x2 %0, %1, %2, %0;" : "+l"(d) : "l"(a), "l"(b));
}
__device__ __forceinline__ unsigned long long add2(unsigned long long a,
                                                   unsigned long long b) {
    unsigned long long r;
    asm("add.rn.f32x2 %0, %1, %2;" : "=l"(r) : "l"(a), "l"(b));
    return r;
}
__device__ __forceinline__ float2 up2(unsigned long long v) {
    float2 f;
    asm("mov.b64 {%0, %1}, %2;" : "=f"(f.x), "=f"(f.y) : "l"(v));
    return f;
}
__device__ __forceinline__ float4 h4_to_f4(uint2 u) {
    __half2 h0 = *reinterpret_cast<__half2*>(&u.x);
    __half2 h1 = *reinterpret_cast<__half2*>(&u.y);
    float2 a = __half22float2(h0);
    float2 c = __half22float2(h1);
    return make_float4(a.x, a.y, c.x, c.y);
}

// ---------------------------------------------------------------------------
// K1: predictions via packed f32x2 FFMA, 4 independent accumulator chains.
// One CTA per n, 256 threads; thread t owns jo in [4t,4t+4).
// ---------------------------------------------------------------------------
__global__ __launch_bounds__(256, 2)
void pred_kernel(const float* __restrict__ x, const float* __restrict__ w) {
    const int n = blockIdx.x;
    const int t = threadIdx.x;

    __shared__ float2 xs2[BB][II];   // (x,x) duplicated pairs, 8 KB
    {
        int b = t >> 2, q = t & 3;
        float4 f = reinterpret_cast<const float4*>(x + ((size_t)b * NN + n) * II)[q];
        xs2[b][4 * q + 0] = make_float2(f.x, f.x);
        xs2[b][4 * q + 1] = make_float2(f.y, f.y);
        xs2[b][4 * q + 2] = make_float2(f.z, f.z);
        xs2[b][4 * q + 3] = make_float2(f.w, f.w);
    }

    float wr[4][16];
    const float4* wp = reinterpret_cast<const float4*>(w + ((size_t)n * JO + 4 * t) * II);
#pragma unroll
    for (int q = 0; q < 4; ++q) {
#pragma unroll
        for (int c = 0; c < 4; ++c) {
            float4 f = wp[q * 4 + c];
            wr[q][4 * c + 0] = f.x; wr[q][4 * c + 1] = f.y;
            wr[q][4 * c + 2] = f.z; wr[q][4 * c + 3] = f.w;
        }
    }
    unsigned long long wp01[16], wp23[16];
#pragma unroll
    for (int i = 0; i < 16; ++i) {
        wp01[i] = pk2(wr[0][i], wr[1][i]);
        wp23[i] = pk2(wr[2][i], wr[3][i]);
    }
    __syncthreads();

    __half* outp = g_predh + (size_t)n * JO + 4 * t;
    uint32_t xbase = (uint32_t)__cvta_generic_to_shared(&xs2[0][0]);

#pragma unroll 4
    for (int b = 0; b < BB; ++b) {
        uint32_t xa = xbase + b * (II * 8);
        unsigned long long a0 = 0ull, a1 = 0ull, a2 = 0ull, a3 = 0ull;
#pragma unroll
        for (int k = 0; k < 8; ++k) {
            unsigned long long xx0, xx1;
            asm("ld.shared.v2.u64 {%0, %1}, [%2];"
                : "=l"(xx0), "=l"(xx1) : "r"(xa + k * 16));
            ffma2(a0, xx0, wp01[2 * k]);
            ffma2(a1, xx1, wp01[2 * k + 1]);
            ffma2(a2, xx0, wp23[2 * k]);
            ffma2(a3, xx1, wp23[2 * k + 1]);
        }
        float2 a01 = up2(add2(a0, a1));
        float2 a23 = up2(add2(a2, a3));
        __half2 b01 = __float22half2_rn(a01);
        __half2 b23 = __float22half2_rn(a23);
        uint2 st;
        st.x = *reinterpret_cast<unsigned int*>(&b01);
        st.y = *reinterpret_cast<unsigned int*>(&b23);
        *reinterpret_cast<uint2*>(outp + (size_t)b * NN * JO) = st;
    }
}

// ---------------------------------------------------------------------------
// K2: iter-0 s partials (uniform coupling). Pure streaming; 128 threads, one
// uint4 (8 jo) per thread per n, unroll-8 for MLP. Writes g_pA (32 chunks).
// ---------------------------------------------------------------------------
__global__ __launch_bounds__(128)
void sum0_kernel() {
    const int chunk = blockIdx.x;   // 0..31
    const int b = blockIdx.y;
    const int t = threadIdx.x;      // octet index 0..127
    const uint4* predp = reinterpret_cast<const uint4*>(
        g_predh + ((size_t)b * NN + (size_t)chunk * CH0) * JO);

    float sacc[8];
#pragma unroll
    for (int e = 0; e < 8; ++e) sacc[e] = 0.f;

#pragma unroll 8
    for (int n = 0; n < CH0; ++n) {
        uint4 r = predp[(size_t)n * 128 + t];
        float2 f0 = __half22float2(*reinterpret_cast<__half2*>(&r.x));
        float2 f1 = __half22float2(*reinterpret_cast<__half2*>(&r.y));
        float2 f2 = __half22float2(*reinterpret_cast<__half2*>(&r.z));
        float2 f3 = __half22float2(*reinterpret_cast<__half2*>(&r.w));
        sacc[0] += f0.x; sacc[1] += f0.y; sacc[2] += f1.x; sacc[3] += f1.y;
        sacc[4] += f2.x; sacc[5] += f2.y; sacc[6] += f3.x; sacc[7] += f3.y;
    }
    const float inv = 1.0f / 32.0f;
    float* dst = g_pA + ((size_t)chunk * BB + b) * JO + t * 8;
    reinterpret_cast<float4*>(dst)[0] =
        make_float4(sacc[0] * inv, sacc[1] * inv, sacc[2] * inv, sacc[3] * inv);
    reinterpret_cast<float4*>(dst)[1] =
        make_float4(sacc[4] * inv, sacc[5] * inv, sacc[6] * inv, sacc[7] * inv);
}

// ---------------------------------------------------------------------------
// K3: reduce partials + squash -> g_v (and optionally d_out).
// ---------------------------------------------------------------------------
template <int NCHIN, bool INA>
__global__ __launch_bounds__(1024)
void v_kernel(float* __restrict__ out) {
    const float* pin = INA ? g_pA : g_pB;
    const int b = blockIdx.x;
    const int t = threadIdx.x;
    float s = 0.f;
#pragma unroll
    for (int k = 0; k < NCHIN; ++k)
        s += pin[((size_t)k * BB + b) * JO + t];
    float sq = s * s;
#pragma unroll
    for (int m = 16; m > 0; m >>= 1)
        sq += __shfl_xor_sync(0xffffffffu, sq, m);
    float scale = (sq / (1.0f + sq)) * rsqrtf(sq + 1e-8f);
    float v = s * scale;
    g_v[b * JO + t] = v;
    if (out) out[b * JO + t] = v;
}

// ---------------------------------------------------------------------------
// K4: routing pass (iters 1,2) with cp.async double-buffered smem pipeline.
// The 16 KB stage for round r+1 is issued BEFORE consuming round r, so DRAM
// stays busy through all barriers / the softmax phase. Consumers read pred
// from smem (no pred registers -> low regs -> 5 CTAs/SM, 80 KB in flight).
//   MODE 1: a = pred.v,  blog = a, softmax(a)
//   MODE 2: a = blog + pred.v,    softmax(a)
// ---------------------------------------------------------------------------
template <int MODE, bool OUTA>
__global__ __launch_bounds__(256, 5)
void pass_kernel() {
    const int chunk = blockIdx.x;
    const int b = blockIdx.y;
    const int t = threadIdx.x;
    const int warp = t >> 5;
    const int lane = t & 31;
    const int j = t >> 3;         // capsule of this thread's quad
    const int sub = t & 7;        // which eighth of capsule j

    __shared__ __align__(16) unsigned char stage[2][STAGE_BYTES];  // 32 KB
    __shared__ float a_part[NB][JJ][8];                            // 8 KB
    __shared__ float c_buf[NB][JJ];                                // 1 KB

    const float4 vv = reinterpret_cast<const float4*>(g_v + b * JO)[t];
    float4 sacc = make_float4(0.f, 0.f, 0.f, 0.f);

    const char* gsrc = reinterpret_cast<const char*>(
        g_predh + ((size_t)b * NN + (size_t)chunk * CHUNK) * JO);
    const uint32_t s0 = (uint32_t)__cvta_generic_to_shared(&stage[0][0]);
    const uint32_t s1 = (uint32_t)__cvta_generic_to_shared(&stage[1][0]);

    // issue round 0
    {
        const char* g = gsrc;
#pragma unroll
        for (int i = 0; i < 4; ++i) {
            uint32_t d = s0 + (i * 256 + t) * 16;
            asm volatile("cp.async.cg.shared.global [%0], [%1], 16;"
                         :: "r"(d), "l"(g + (i * 256 + t) * 16));
        }
        asm volatile("cp.async.commit_group;");
    }

    for (int r = 0; r < NROUND; ++r) {
        if (r + 1 < NROUND) {   // issue round r+1 into the other buffer
            const char* g = gsrc + (size_t)(r + 1) * STAGE_BYTES;
            uint32_t sb = ((r + 1) & 1) ? s1 : s0;
#pragma unroll
            for (int i = 0; i < 4; ++i) {
                uint32_t d = sb + (i * 256 + t) * 16;
                asm volatile("cp.async.cg.shared.global [%0], [%1], 16;"
                             :: "r"(d), "l"(g + (i * 256 + t) * 16));
            }
            asm volatile("cp.async.commit_group;");
            asm volatile("cp.async.wait_group 1;");
        } else {
            asm volatile("cp.async.wait_group 0;");
        }
        __syncthreads();   // stage r visible to all threads

        const uint32_t sb = (r & 1) ? s1 : s0;

        // dot partials -> a_part
#pragma unroll
        for (int k = 0; k < NB; ++k) {
            uint2 u;
            asm("ld.shared.v2.u32 {%0, %1}, [%2];"
                : "=r"(u.x), "=r"(u.y) : "r"(sb + k * (JO * 2) + t * 8));
            float4 p = h4_to_f4(u);
            a_part[k][j][sub] =
                p.x * vv.x + p.y * vv.y + p.z * vv.z + p.w * vv.w;
        }
        __syncthreads();

        {   // warp k: finish dot for n = base+k, blog, softmax over 32 j
            const int k = warp;
            const int n = chunk * CHUNK + r * NB + k;
            float4 q0 = *reinterpret_cast<const float4*>(&a_part[k][lane][0]);
            float4 q1 = *reinterpret_cast<const float4*>(&a_part[k][lane][4]);
            float a = ((q0.x + q0.y) + (q0.z + q0.w)) +
                      ((q1.x + q1.y) + (q1.z + q1.w));
            size_t bidx = ((size_t)b * NN + n) * JJ + lane;
            if (MODE == 2) a += g_blog[bidx];
            else           g_blog[bidx] = a;     // b1 = agreement (b0 = 0)
            float m = a;
#pragma unroll
            for (int s = 16; s > 0; s >>= 1)
                m = fmaxf(m, __shfl_xor_sync(0xffffffffu, m, s));
            float e = __expf(a - m);
            float ssum = e;
#pragma unroll
            for (int s = 16; s > 0; s >>= 1)
                ssum += __shfl_xor_sync(0xffffffffu, ssum, s);
            c_buf[k][lane] = e / ssum;
        }
        __syncthreads();

        // c-weighted accumulation (re-read pred from smem)
#pragma unroll
        for (int k = 0; k < NB; ++k) {
            float c = c_buf[k][j];
            uint2 u;
            asm("ld.shared.v2.u32 {%0, %1}, [%2];"
                : "=r"(u.x), "=r"(u.y) : "r"(sb + k * (JO * 2) + t * 8));
            float4 p = h4_to_f4(u);
            sacc.x = fmaf(c, p.x, sacc.x);
            sacc.y = fmaf(c, p.y, sacc.y);
            sacc.z = fmaf(c, p.z, sacc.z);
            sacc.w = fmaf(c, p.w, sacc.w);
        }
        __syncthreads();   // stage r free before round r+1 issues over it
    }

    float* pout = OUTA ? g_pA : g_pB;
    reinterpret_cast<float4*>(pout + ((size_t)chunk * BB + b) * JO)[t] = sacc;
}

// ---------------------------------------------------------------------------
extern "C" void kernel_launch(void* const* d_in, const int* in_sizes, int n_in,
                              void* d_out, int out_size) {
    const float* x = (const float*)d_in[0];   // [64, 2048, 16] f32
    const float* w = (const float*)d_in[1];   // [2048, 32, 32, 16] f32
    float* out = (float*)d_out;               // [64, 32, 32] f32

    pred_kernel<<<NN, 256>>>(x, w);
    sum0_kernel<<<dim3(NCH0, BB), 128>>>();            // s0 partials -> A (32)
    v_kernel<NCH0, true><<<BB, 1024>>>(nullptr);       // v0
    pass_kernel<1, false><<<dim3(16, BB), 256>>>();    // b1, c1, s1 -> B (16)
    v_kernel<16, false><<<BB, 1024>>>(nullptr);        // v1
    pass_kernel<2, true><<<dim3(16, BB), 256>>>();     // b2, c2, s2 -> A (16)
    v_kernel<16, true><<<BB, 1024>>>(out);             // v2 -> output
}

// round 10
// speedup vs baseline: 1.1148x; 1.0709x over previous
#include <cuda_runtime.h>
#include <cuda_fp16.h>
#include <cstddef>
#include <cstdint>

#define BB 64
#define NN 2048
#define II 16
#define JJ 32
#define OO 32
#define JO 1024      // J*O
#define NB 8         // n's per stage/round in pass_kernel (== #warps)
#define CHUNK 128    // n's per pass CTA (16 chunks)
#define NROUND 16    // CHUNK / NB
#define STAGE_BYTES (NB * JO * 2)   // 16 KB
#define PASS_DYN_SMEM (3 * STAGE_BYTES + 4096 + 1024)
#define NCH0 32      // sum0 chunks
#define CH0 64       // n's per sum0 CTA
#define S0_STAGE (8 * 128 * 16)     // 16 KB (8 n x 128 threads x 16B)

// Scratch (allocation-free rule: __device__ globals).
__device__ __half g_predh[(size_t)BB * NN * JO];        // 256 MB fp16 predictions
__device__ float g_pA[(size_t)NCH0 * BB * JO];          // partial buffer A (8 MB)
__device__ float g_pB[(size_t)16 * BB * JO];            // partial buffer B (4 MB)
__device__ float g_v[BB * JO];                          // squashed v
__device__ float g_blog[(size_t)BB * NN * JJ];          // routing logits (pass1 -> pass2)

// ---- packed fp32x2 helpers (sm_103a) --------------------------------------
__device__ __forceinline__ unsigned long long pk2(float a, float b) {
    unsigned long long r;
    asm("mov.b64 %0, {%1, %2};" : "=l"(r) : "f"(a), "f"(b));
    return r;
}
__device__ __forceinline__ void ffma2(unsigned long long& d,
                                      unsigned long long a,
                                      unsigned long long b) {
    asm("fma.rn.f32x2 %0, %1, %2, %0;" : "+l"(d) : "l"(a), "l"(b));
}
__device__ __forceinline__ unsigned long long add2(unsigned long long a,
                                                   unsigned long long b) {
    unsigned long long r;
    asm("add.rn.f32x2 %0, %1, %2;" : "=l"(r) : "l"(a), "l"(b));
    return r;
}
__device__ __forceinline__ float2 up2(unsigned long long v) {
    float2 f;
    asm("mov.b64 {%0, %1}, %2;" : "=f"(f.x), "=f"(f.y) : "l"(v));
    return f;
}
__device__ __forceinline__ float4 h4_to_f4(uint2 u) {
    __half2 h0 = *reinterpret_cast<__half2*>(&u.x);
    __half2 h1 = *reinterpret_cast<__half2*>(&u.y);
    float2 a = __half22float2(h0);
    float2 c = __half22float2(h1);
    return make_float4(a.x, a.y, c.x, c.y);
}

// ---------------------------------------------------------------------------
// K1: predictions via packed f32x2 FFMA, 4 independent accumulator chains.
// One CTA per n, 256 threads; thread t owns jo in [4t,4t+4).
// ---------------------------------------------------------------------------
__global__ __launch_bounds__(256, 2)
void pred_kernel(const float* __restrict__ x, const float* __restrict__ w) {
    const int n = blockIdx.x;
    const int t = threadIdx.x;

    __shared__ float2 xs2[BB][II];   // (x,x) duplicated pairs, 8 KB
    {
        int b = t >> 2, q = t & 3;
        float4 f = reinterpret_cast<const float4*>(x + ((size_t)b * NN + n) * II)[q];
        xs2[b][4 * q + 0] = make_float2(f.x, f.x);
        xs2[b][4 * q + 1] = make_float2(f.y, f.y);
        xs2[b][4 * q + 2] = make_float2(f.z, f.z);
        xs2[b][4 * q + 3] = make_float2(f.w, f.w);
    }

    float wr[4][16];
    const float4* wp = reinterpret_cast<const float4*>(w + ((size_t)n * JO + 4 * t) * II);
#pragma unroll
    for (int q = 0; q < 4; ++q) {
#pragma unroll
        for (int c = 0; c < 4; ++c) {
            float4 f = wp[q * 4 + c];
            wr[q][4 * c + 0] = f.x; wr[q][4 * c + 1] = f.y;
            wr[q][4 * c + 2] = f.z; wr[q][4 * c + 3] = f.w;
        }
    }
    unsigned long long wp01[16], wp23[16];
#pragma unroll
    for (int i = 0; i < 16; ++i) {
        wp01[i] = pk2(wr[0][i], wr[1][i]);
        wp23[i] = pk2(wr[2][i], wr[3][i]);
    }
    __syncthreads();

    __half* outp = g_predh + (size_t)n * JO + 4 * t;
    uint32_t xbase = (uint32_t)__cvta_generic_to_shared(&xs2[0][0]);

#pragma unroll 4
    for (int b = 0; b < BB; ++b) {
        uint32_t xa = xbase + b * (II * 8);
        unsigned long long a0 = 0ull, a1 = 0ull, a2 = 0ull, a3 = 0ull;
#pragma unroll
        for (int k = 0; k < 8; ++k) {
            unsigned long long xx0, xx1;
            asm("ld.shared.v2.u64 {%0, %1}, [%2];"
                : "=l"(xx0), "=l"(xx1) : "r"(xa + k * 16));
            ffma2(a0, xx0, wp01[2 * k]);
            ffma2(a1, xx1, wp01[2 * k + 1]);
            ffma2(a2, xx0, wp23[2 * k]);
            ffma2(a3, xx1, wp23[2 * k + 1]);
        }
        float2 a01 = up2(add2(a0, a1));
        float2 a23 = up2(add2(a2, a3));
        __half2 b01 = __float22half2_rn(a01);
        __half2 b23 = __float22half2_rn(a23);
        uint2 st;
        st.x = *reinterpret_cast<unsigned int*>(&b01);
        st.y = *reinterpret_cast<unsigned int*>(&b23);
        *reinterpret_cast<uint2*>(outp + (size_t)b * NN * JO) = st;
    }
}

// ---------------------------------------------------------------------------
// K2: iter-0 s partials. Barrier-free per-thread 3-stage cp.async pipeline:
// each thread consumes only the bytes it copied, so cp.async.wait_group alone
// orders everything (zero __syncthreads). 2 stages (256 B/thread) always in
// flight. 128 threads; thread t owns jo octet [8t, 8t+8).
// ---------------------------------------------------------------------------
__global__ __launch_bounds__(128)
void sum0_kernel() {
    __shared__ __align__(16) unsigned char st[3][S0_STAGE];   // 48 KB
    const int chunk = blockIdx.x;   // 0..31
    const int b = blockIdx.y;
    const int t = threadIdx.x;      // octet index 0..127

    const char* gsrc = reinterpret_cast<const char*>(
        g_predh + ((size_t)b * NN + (size_t)chunk * CH0) * JO);
    const uint32_t sb0 = (uint32_t)__cvta_generic_to_shared(&st[0][0]);

    auto issue = [&](int s) {
        const char* g = gsrc + (size_t)s * S0_STAGE;
        uint32_t d = sb0 + (s % 3) * S0_STAGE;
#pragma unroll
        for (int k = 0; k < 8; ++k) {
            uint32_t off = (k * 128 + t) * 16;
            asm volatile("cp.async.cg.shared.global [%0], [%1], 16;"
                         :: "r"(d + off), "l"(g + off));
        }
        asm volatile("cp.async.commit_group;");
    };

    issue(0); issue(1);
    float sacc[8];
#pragma unroll
    for (int e = 0; e < 8; ++e) sacc[e] = 0.f;

    for (int s = 0; s < 8; ++s) {
        if (s + 2 < 8) { issue(s + 2); asm volatile("cp.async.wait_group 2;"); }
        else if (s + 1 < 8) { asm volatile("cp.async.wait_group 1;"); }
        else { asm volatile("cp.async.wait_group 0;"); }

        const unsigned char* sp = &st[s % 3][0];
#pragma unroll
        for (int k = 0; k < 8; ++k) {
            uint4 r = *reinterpret_cast<const uint4*>(sp + (k * 128 + t) * 16);
            float2 f0 = __half22float2(*reinterpret_cast<__half2*>(&r.x));
            float2 f1 = __half22float2(*reinterpret_cast<__half2*>(&r.y));
            float2 f2 = __half22float2(*reinterpret_cast<__half2*>(&r.z));
            float2 f3 = __half22float2(*reinterpret_cast<__half2*>(&r.w));
            sacc[0] += f0.x; sacc[1] += f0.y; sacc[2] += f1.x; sacc[3] += f1.y;
            sacc[4] += f2.x; sacc[5] += f2.y; sacc[6] += f3.x; sacc[7] += f3.y;
        }
    }
    const float inv = 1.0f / 32.0f;
    float* dst = g_pA + ((size_t)chunk * BB + b) * JO + t * 8;
    reinterpret_cast<float4*>(dst)[0] =
        make_float4(sacc[0] * inv, sacc[1] * inv, sacc[2] * inv, sacc[3] * inv);
    reinterpret_cast<float4*>(dst)[1] =
        make_float4(sacc[4] * inv, sacc[5] * inv, sacc[6] * inv, sacc[7] * inv);
}

// ---------------------------------------------------------------------------
// K3: reduce partials + squash -> g_v (and optionally d_out).
// ---------------------------------------------------------------------------
template <int NCHIN, bool INA>
__global__ __launch_bounds__(1024)
void v_kernel(float* __restrict__ out) {
    const float* pin = INA ? g_pA : g_pB;
    const int b = blockIdx.x;
    const int t = threadIdx.x;
    float s = 0.f;
#pragma unroll
    for (int k = 0; k < NCHIN; ++k)
        s += pin[((size_t)k * BB + b) * JO + t];
    float sq = s * s;
#pragma unroll
    for (int m = 16; m > 0; m >>= 1)
        sq += __shfl_xor_sync(0xffffffffu, sq, m);
    float scale = (sq / (1.0f + sq)) * rsqrtf(sq + 1e-8f);
    float v = s * scale;
    g_v[b * JO + t] = v;
    if (out) out[b * JO + t] = v;
}

// ---------------------------------------------------------------------------
// K4: routing pass (iters 1,2) with 3-stage cp.async ring: wait_group 2 keeps
// stages r+1 AND r+2 (32 KB/CTA) in flight while round r is consumed, 4
// CTAs/SM => ~128 KB in flight per SM. a_part shrunk to 4 KB via one
// pre-reduce shuffle so dynamic smem = 53.25 KB fits 4 CTAs.
//   MODE 1: a = pred.v,  blog = a, softmax(a)
//   MODE 2: a = blog + pred.v,    softmax(a)
// ---------------------------------------------------------------------------
template <int MODE, bool OUTA>
__global__ __launch_bounds__(256)
void pass_kernel() {
    extern __shared__ __align__(16) unsigned char dyn[];
    float (*a_part)[JJ][4] = reinterpret_cast<float(*)[JJ][4]>(dyn + 3 * STAGE_BYTES);
    float (*c_buf)[JJ] = reinterpret_cast<float(*)[JJ]>(dyn + 3 * STAGE_BYTES + 4096);

    const int chunk = blockIdx.x;
    const int b = blockIdx.y;
    const int t = threadIdx.x;
    const int warp = t >> 5;
    const int lane = t & 31;
    const int j = t >> 3;         // capsule of this thread's quad
    const int sub = t & 7;        // which eighth of capsule j

    const float4 vv = reinterpret_cast<const float4*>(g_v + b * JO)[t];
    float4 sacc = make_float4(0.f, 0.f, 0.f, 0.f);

    const char* gsrc = reinterpret_cast<const char*>(
        g_predh + ((size_t)b * NN + (size_t)chunk * CHUNK) * JO);
    const uint32_t sb0 = (uint32_t)__cvta_generic_to_shared(dyn);

    auto issue = [&](int r) {
        const char* g = gsrc + (size_t)r * STAGE_BYTES;
        uint32_t d = sb0 + (r % 3) * STAGE_BYTES;
#pragma unroll
        for (int i = 0; i < 4; ++i) {
            uint32_t off = (i * 256 + t) * 16;
            asm volatile("cp.async.cg.shared.global [%0], [%1], 16;"
                         :: "r"(d + off), "l"(g + off));
        }
        asm volatile("cp.async.commit_group;");
    };

    issue(0); issue(1);

    for (int r = 0; r < NROUND; ++r) {
        if (r + 2 < NROUND) { issue(r + 2); asm volatile("cp.async.wait_group 2;"); }
        else if (r + 1 < NROUND) { asm volatile("cp.async.wait_group 1;"); }
        else { asm volatile("cp.async.wait_group 0;"); }
        __syncthreads();   // stage r visible to all threads

        const uint32_t sb = sb0 + (r % 3) * STAGE_BYTES;

        // phase A: partial dots, one pre-reduce shuffle, half-lanes write
#pragma unroll
        for (int k = 0; k < NB; ++k) {
            uint2 u;
            asm("ld.shared.v2.u32 {%0, %1}, [%2];"
                : "=r"(u.x), "=r"(u.y) : "r"(sb + k * (JO * 2) + t * 8));
            float4 p = h4_to_f4(u);
            float d = p.x * vv.x + p.y * vv.y + p.z * vv.z + p.w * vv.w;
            d += __shfl_xor_sync(0xffffffffu, d, 4);
            if (sub < 4) a_part[k][j][sub] = d;
        }
        __syncthreads();

        {   // phase B: warp k finishes dot for n = base+k, blog, softmax
            const int k = warp;
            const int n = chunk * CHUNK + r * NB + k;
            float4 q = *reinterpret_cast<const float4*>(&a_part[k][lane][0]);
            float a = (q.x + q.y) + (q.z + q.w);
            size_t bidx = ((size_t)b * NN + n) * JJ + lane;
            if (MODE == 2) a += g_blog[bidx];
            else           g_blog[bidx] = a;     // b1 = agreement (b0 = 0)
            float m = a;
#pragma unroll
            for (int s = 16; s > 0; s >>= 1)
                m = fmaxf(m, __shfl_xor_sync(0xffffffffu, m, s));
            float e = __expf(a - m);
            float ssum = e;
#pragma unroll
            for (int s = 16; s > 0; s >>= 1)
                ssum += __shfl_xor_sync(0xffffffffu, ssum, s);
            c_buf[k][lane] = e / ssum;
        }
        __syncthreads();

        // phase C: c-weighted accumulation (re-read pred from smem)
#pragma unroll
        for (int k = 0; k < NB; ++k) {
            float c = c_buf[k][j];
            uint2 u;
            asm("ld.shared.v2.u32 {%0, %1}, [%2];"
                : "=r"(u.x), "=r"(u.y) : "r"(sb + k * (JO * 2) + t * 8));
            float4 p = h4_to_f4(u);
            sacc.x = fmaf(c, p.x, sacc.x);
            sacc.y = fmaf(c, p.y, sacc.y);
            sacc.z = fmaf(c, p.z, sacc.z);
            sacc.w = fmaf(c, p.w, sacc.w);
        }
        __syncthreads();   // stage r free before round r+1 issues over it
    }

    float* pout = OUTA ? g_pA : g_pB;
    reinterpret_cast<float4*>(pout + ((size_t)chunk * BB + b) * JO)[t] = sacc;
}

// ---------------------------------------------------------------------------
extern "C" void kernel_launch(void* const* d_in, const int* in_sizes, int n_in,
                              void* d_out, int out_size) {
    const float* x = (const float*)d_in[0];   // [64, 2048, 16] f32
    const float* w = (const float*)d_in[1];   // [2048, 32, 32, 16] f32
    float* out = (float*)d_out;               // [64, 32, 32] f32

    cudaFuncSetAttribute(pass_kernel<1, false>,
                         cudaFuncAttributeMaxDynamicSharedMemorySize, PASS_DYN_SMEM);
    cudaFuncSetAttribute(pass_kernel<2, true>,
                         cudaFuncAttributeMaxDynamicSharedMemorySize, PASS_DYN_SMEM);

    pred_kernel<<<NN, 256>>>(x, w);
    sum0_kernel<<<dim3(NCH0, BB), 128>>>();                      // s0 -> A (32)
    v_kernel<NCH0, true><<<BB, 1024>>>(nullptr);                 // v0
    pass_kernel<1, false><<<dim3(16, BB), 256, PASS_DYN_SMEM>>>();  // s1 -> B
    v_kernel<16, false><<<BB, 1024>>>(nullptr);                  // v1
    pass_kernel<2, true><<<dim3(16, BB), 256, PASS_DYN_SMEM>>>();   // s2 -> A
    v_kernel<16, true><<<BB, 1024>>>(out);                       // v2 -> output
}